// round 7
// baseline (speedup 1.0000x reference)
#include <cuda_runtime.h>
#include <math.h>
#include <stdint.h>

// Shapes (fixed by the problem)
#define BB   4
#define TT   2048
#define CC   1024
#define NH   16
#define HD   64
#define MM   (BB*TT)          // 8192
#define N_QKV (3*CC)          // 3072

// ---------------------------------------------------------------------------
// Scratch (device globals; no allocation allowed)
// ---------------------------------------------------------------------------
__device__ float g_Q[BB*NH*TT*HD];   // (B,H,T,D)  tf32-rounded, Q pre-scaled
__device__ float g_K[BB*NH*TT*HD];
__device__ float g_V[BB*NH*TT*HD];
__device__ float g_O[MM*CC];         // (B,T,C)    tf32-rounded
__device__ float g_X32[MM*CC];       // tf32-rounded x
__device__ float g_W1[CC*N_QKV];     // tf32-rounded W_qkv
__device__ float g_W2[CC*CC];        // tf32-rounded W_out

// ---------------------------------------------------------------------------
// Helpers
// ---------------------------------------------------------------------------
__device__ __forceinline__ uint32_t f2tf32(float f) {
    uint32_t r;
    asm("cvt.rna.tf32.f32 %0, %1;" : "=r"(r) : "f"(f));
    return r;
}

__device__ __forceinline__ void mma8(float c[4], const uint32_t a[4],
                                     uint32_t b0, uint32_t b1) {
    asm volatile(
        "mma.sync.aligned.m16n8k8.row.col.f32.tf32.tf32.f32 "
        "{%0,%1,%2,%3},{%4,%5,%6,%7},{%8,%9},{%0,%1,%2,%3};"
        : "+f"(c[0]), "+f"(c[1]), "+f"(c[2]), "+f"(c[3])
        : "r"(a[0]), "r"(a[1]), "r"(a[2]), "r"(a[3]), "r"(b0), "r"(b1));
}

__device__ __forceinline__ void cp16(uint32_t dst, const void* src) {
    asm volatile("cp.async.cg.shared.global [%0], [%1], 16;"
                 :: "r"(dst), "l"(src));
}
#define CP_COMMIT() asm volatile("cp.async.commit_group;")
#define CP_WAIT(n)  asm volatile("cp.async.wait_group %0;" :: "n"(n))

// ---------------------------------------------------------------------------
// Pre-round kernel: out = tf32(in), elementwise. which selects dst symbol.
// ---------------------------------------------------------------------------
__global__ void round_tf32(const float* __restrict__ in, int which, int n) {
    float* out = (which == 0) ? g_X32 : (which == 1) ? g_W1 : g_W2;
    int i = (blockIdx.x * blockDim.x + threadIdx.x) * 4;
    if (i >= n) return;
    float4 v = *(const float4*)(in + i);
    v.x = __uint_as_float(f2tf32(v.x));
    v.y = __uint_as_float(f2tf32(v.y));
    v.z = __uint_as_float(f2tf32(v.z));
    v.w = __uint_as_float(f2tf32(v.w));
    *(float4*)(out + i) = v;
}

// ---------------------------------------------------------------------------
// TF32 GEMM, cp.async 4-stage pipeline.
// BM=BN=128, BK=16, 128 threads (4 warps, 2x2), warp tile 64x64.
// MODE 0: A=g_X32, W=g_W1, scatter rounded into g_Q/g_K/g_V (Q pre-scaled).
// MODE 1: A=g_O,   W=g_W2, plain fp32 store to C.
// ---------------------------------------------------------------------------
#define PADA 20
#define PADB 136
#define STG  4
#define GEMM_SMEM (STG * (128*PADA + 16*PADB) * 4)

template <int MODE>
__global__ __launch_bounds__(128) void gemm_tc(const float* __restrict__ bias,
                                               float* __restrict__ C) {
    extern __shared__ float smem[];
    float* As = smem;                       // [STG][128*PADA]
    float* Bs = smem + STG * 128 * PADA;    // [STG][16*PADB]

    const float* A = (MODE == 0) ? (const float*)g_X32 : (const float*)g_O;
    const float* W = (MODE == 0) ? (const float*)g_W1  : (const float*)g_W2;
    const int   N  = (MODE == 0) ? N_QKV : CC;

    const int tid  = threadIdx.x;
    const int lane = tid & 31;
    const int g    = lane >> 2;
    const int q    = lane & 3;
    const int wid  = tid >> 5;
    const int wm   = (wid & 1) * 64;
    const int wn   = (wid >> 1) * 64;

    const int bm = blockIdx.y * 128;
    const int bn = blockIdx.x * 128;

    const int brow = tid >> 3;          // 0..15
    const int bcol = (tid & 7) * 16;    // 0..112

    const uint32_t sA = (uint32_t)__cvta_generic_to_shared(As);
    const uint32_t sB = (uint32_t)__cvta_generic_to_shared(Bs);

    auto fill = [&](int s, int k0) {
        const float* ap = A + (size_t)(bm + tid) * CC + k0;
        uint32_t da = sA + (uint32_t)(s * 128 * PADA + tid * PADA) * 4;
        cp16(da,      ap);
        cp16(da + 16, ap + 4);
        cp16(da + 32, ap + 8);
        cp16(da + 48, ap + 12);
        const float* wp = W + (size_t)(k0 + brow) * N + bn + bcol;
        uint32_t db = sB + (uint32_t)(s * 16 * PADB + brow * PADB + bcol) * 4;
        cp16(db,      wp);
        cp16(db + 16, wp + 4);
        cp16(db + 32, wp + 8);
        cp16(db + 48, wp + 12);
    };

    float c[4][8][4];
    #pragma unroll
    for (int mt = 0; mt < 4; mt++)
        #pragma unroll
        for (int nt = 0; nt < 8; nt++)
            #pragma unroll
            for (int r = 0; r < 4; r++) c[mt][nt][r] = 0.0f;

    const int NT = CC / 16;   // 64
    fill(0, 0);  CP_COMMIT();
    fill(1, 16); CP_COMMIT();
    fill(2, 32); CP_COMMIT();

    for (int t = 0; t < NT; t++) {
        CP_WAIT(2);
        __syncthreads();

        const int tn = t + 3;
        if (tn < NT) fill(tn & (STG - 1), tn * 16);
        CP_COMMIT();

        const uint32_t* Au = (const uint32_t*)(As + (t & (STG - 1)) * 128 * PADA);
        const uint32_t* Bu = (const uint32_t*)(Bs + (t & (STG - 1)) * 16 * PADB);

        #pragma unroll
        for (int kk = 0; kk < 16; kk += 8) {
            uint32_t af[4][4];
            #pragma unroll
            for (int mt = 0; mt < 4; mt++) {
                const int rb = wm + mt * 16;
                af[mt][0] = Au[(rb + g)     * PADA + kk + q];
                af[mt][1] = Au[(rb + g + 8) * PADA + kk + q];
                af[mt][2] = Au[(rb + g)     * PADA + kk + q + 4];
                af[mt][3] = Au[(rb + g + 8) * PADA + kk + q + 4];
            }
            #pragma unroll
            for (int nt = 0; nt < 8; nt++) {
                uint32_t bf0 = Bu[(kk + q)     * PADB + wn + nt * 8 + g];
                uint32_t bf1 = Bu[(kk + q + 4) * PADB + wn + nt * 8 + g];
                #pragma unroll
                for (int mt = 0; mt < 4; mt++)
                    mma8(c[mt][nt], af[mt], bf0, bf1);
            }
        }
    }

    // epilogue
    #pragma unroll
    for (int mt = 0; mt < 4; mt++) {
        #pragma unroll
        for (int nt = 0; nt < 8; nt++) {
            #pragma unroll
            for (int r = 0; r < 4; r++) {
                int row = bm + wm + mt * 16 + g + (r >> 1) * 8;
                int col = bn + wn + nt * 8 + q * 2 + (r & 1);
                float v = c[mt][nt][r] + bias[col];
                if (MODE == 0) {
                    int b  = row >> 11;
                    int tt = row & 2047;
                    int which = col >> 10;
                    int cc = col & 1023;
                    int h = cc >> 6;
                    int d = cc & 63;
                    float* dst = (which == 0) ? g_Q : (which == 1) ? g_K : g_V;
                    float vv = (which == 0) ? v * 0.125f : v;  // pre-scale Q
                    dst[(((size_t)(b * NH + h) * TT) + tt) * HD + d] =
                        __uint_as_float(f2tf32(vv));
                } else {
                    C[(size_t)row * CC + col] = v;
                }
            }
        }
    }
}

// ---------------------------------------------------------------------------
// Flash attention, tf32 mma, cp.async double-buffered KV.
// 256 threads (8 warps), 128 queries/CTA (16 rows per warp), 64-key KV tiles.
// Q/K/V pre-rounded (Q pre-scaled) -> fills are pure copies.
// fillkv copies the FULL 64x64 tile (4 cp16 per operand per thread).
// ---------------------------------------------------------------------------
#define KP 68
#define VP 72
#define PP 68
#define FLASH_SMEM ((2*64*KP + 2*64*VP + 128*PP) * 4)

__global__ __launch_bounds__(256) void flash_tc() {
    extern __shared__ float fsm[];
    float* Ks = fsm;                          // [2][64*KP]
    float* Vs = fsm + 2 * 64 * KP;            // [2][64*VP]
    float* Ps = fsm + 2 * 64 * KP + 2 * 64 * VP;  // [128*PP]

    const int tid  = threadIdx.x;
    const int lane = tid & 31;
    const int g    = lane >> 2;
    const int q    = lane & 3;
    const int w    = tid >> 5;
    const int wrow = w * 16;

    const int qt = (int)(gridDim.x - 1) - (int)blockIdx.x;  // big tiles first
    const int bh = blockIdx.y;
    const int nkv = 2 * qt + 2;

    // Q fragments (pre-rounded + pre-scaled in gmem)
    const float* Qp = g_Q + ((size_t)bh * TT + qt * 128) * HD;
    uint32_t qa[8][4];
    #pragma unroll
    for (int ks = 0; ks < 8; ks++) {
        const int r0 = wrow + g, r1 = r0 + 8;
        const int c0 = ks * 8 + q, c1 = c0 + 4;
        qa[ks][0] = __float_as_uint(Qp[r0 * HD + c0]);
        qa[ks][1] = __float_as_uint(Qp[r1 * HD + c0]);
        qa[ks][2] = __float_as_uint(Qp[r0 * HD + c1]);
        qa[ks][3] = __float_as_uint(Qp[r1 * HD + c1]);
    }

    float o[8][4];
    #pragma unroll
    for (int nt = 0; nt < 8; nt++)
        #pragma unroll
        for (int r = 0; r < 4; r++) o[nt][r] = 0.0f;
    float m0 = -INFINITY, m1 = -INFINITY, l0 = 0.0f, l1 = 0.0f;

    const uint32_t sK = (uint32_t)__cvta_generic_to_shared(Ks);
    const uint32_t sV = (uint32_t)__cvta_generic_to_shared(Vs);
    const int frow = tid >> 2;          // 0..63
    const int fcol = (tid & 3) * 16;    // 0,16,32,48 (float index)

    auto fillkv = [&](int buf, int kti) {
        const float* Kp = g_K + ((size_t)bh * TT + kti * 64) * HD
                          + frow * HD + fcol;
        const float* Vp = g_V + ((size_t)bh * TT + kti * 64) * HD
                          + frow * HD + fcol;
        uint32_t dk = sK + (uint32_t)(buf * 64 * KP + frow * KP + fcol) * 4;
        uint32_t dv = sV + (uint32_t)(buf * 64 * VP + frow * VP + fcol) * 4;
        cp16(dk,      Kp);
        cp16(dk + 16, Kp + 4);
        cp16(dk + 32, Kp + 8);
        cp16(dk + 48, Kp + 12);
        cp16(dv,      Vp);
        cp16(dv + 16, Vp + 4);
        cp16(dv + 32, Vp + 8);
        cp16(dv + 48, Vp + 12);
    };

    fillkv(0, 0); CP_COMMIT();

    for (int ktt = 0; ktt < nkv; ktt++) {
        if (ktt + 1 < nkv) fillkv((ktt + 1) & 1, ktt + 1);
        CP_COMMIT();
        CP_WAIT(1);
        __syncthreads();

        const bool full_skip = (ktt * 64) > (qt * 128 + wrow + 15);
        if (!full_skip) {
            const uint32_t* Kb = (const uint32_t*)(Ks + (ktt & 1) * 64 * KP);
            const uint32_t* Vb = (const uint32_t*)(Vs + (ktt & 1) * 64 * VP);

            // S = Q K^T
            float s[8][4];
            #pragma unroll
            for (int nt = 0; nt < 8; nt++)
                #pragma unroll
                for (int r = 0; r < 4; r++) s[nt][r] = 0.0f;

            #pragma unroll
            for (int kk = 0; kk < 8; kk++) {
                #pragma unroll
                for (int nt = 0; nt < 8; nt++) {
                    uint32_t b0 = Kb[(nt * 8 + g) * KP + kk * 8 + q];
                    uint32_t b1 = Kb[(nt * 8 + g) * KP + kk * 8 + q + 4];
                    mma8(s[nt], qa[kk], b0, b1);
                }
            }

            // causal mask (global indices)
            const int rowg0 = qt * 128 + wrow + g;
            const int rowg1 = rowg0 + 8;
            if (ktt * 64 + 63 > qt * 128 + wrow) {
                #pragma unroll
                for (int nt = 0; nt < 8; nt++) {
                    const int c0 = ktt * 64 + nt * 8 + 2 * q;
                    if (c0     > rowg0) s[nt][0] = -INFINITY;
                    if (c0 + 1 > rowg0) s[nt][1] = -INFINITY;
                    if (c0     > rowg1) s[nt][2] = -INFINITY;
                    if (c0 + 1 > rowg1) s[nt][3] = -INFINITY;
                }
            }

            // online softmax (quad reduction)
            float mx0 = -INFINITY, mx1 = -INFINITY;
            #pragma unroll
            for (int nt = 0; nt < 8; nt++) {
                mx0 = fmaxf(mx0, fmaxf(s[nt][0], s[nt][1]));
                mx1 = fmaxf(mx1, fmaxf(s[nt][2], s[nt][3]));
            }
            mx0 = fmaxf(mx0, __shfl_xor_sync(0xffffffffu, mx0, 1));
            mx0 = fmaxf(mx0, __shfl_xor_sync(0xffffffffu, mx0, 2));
            mx1 = fmaxf(mx1, __shfl_xor_sync(0xffffffffu, mx1, 1));
            mx1 = fmaxf(mx1, __shfl_xor_sync(0xffffffffu, mx1, 2));

            float mn0 = fmaxf(m0, mx0), mn1 = fmaxf(m1, mx1);
            float corr0 = __expf(m0 - mn0), corr1 = __expf(m1 - mn1);
            m0 = mn0; m1 = mn1;

            float rs0 = 0.0f, rs1 = 0.0f;
            #pragma unroll
            for (int nt = 0; nt < 8; nt++) {
                s[nt][0] = __expf(s[nt][0] - m0); rs0 += s[nt][0];
                s[nt][1] = __expf(s[nt][1] - m0); rs0 += s[nt][1];
                s[nt][2] = __expf(s[nt][2] - m1); rs1 += s[nt][2];
                s[nt][3] = __expf(s[nt][3] - m1); rs1 += s[nt][3];
            }
            rs0 += __shfl_xor_sync(0xffffffffu, rs0, 1);
            rs0 += __shfl_xor_sync(0xffffffffu, rs0, 2);
            rs1 += __shfl_xor_sync(0xffffffffu, rs1, 1);
            rs1 += __shfl_xor_sync(0xffffffffu, rs1, 2);
            l0 = l0 * corr0 + rs0;
            l1 = l1 * corr1 + rs1;

            #pragma unroll
            for (int nt = 0; nt < 8; nt++) {
                o[nt][0] *= corr0; o[nt][1] *= corr0;
                o[nt][2] *= corr1; o[nt][3] *= corr1;
            }

            // P -> smem (own warp rows; no barrier)
            uint32_t* Pu = (uint32_t*)Ps;
            #pragma unroll
            for (int nt = 0; nt < 8; nt++) {
                const int c0 = nt * 8 + 2 * q;
                uint2 p0 = make_uint2(f2tf32(s[nt][0]), f2tf32(s[nt][1]));
                uint2 p1 = make_uint2(f2tf32(s[nt][2]), f2tf32(s[nt][3]));
                *(uint2*)&Pu[(wrow + g)     * PP + c0] = p0;
                *(uint2*)&Pu[(wrow + g + 8) * PP + c0] = p1;
            }

            // O += P V
            #pragma unroll
            for (int kk = 0; kk < 8; kk++) {
                uint32_t a[4];
                a[0] = Pu[(wrow + g)     * PP + kk * 8 + q];
                a[1] = Pu[(wrow + g + 8) * PP + kk * 8 + q];
                a[2] = Pu[(wrow + g)     * PP + kk * 8 + q + 4];
                a[3] = Pu[(wrow + g + 8) * PP + kk * 8 + q + 4];
                #pragma unroll
                for (int nt = 0; nt < 8; nt++) {
                    uint32_t b0 = Vb[(kk * 8 + q)     * VP + nt * 8 + g];
                    uint32_t b1 = Vb[(kk * 8 + q + 4) * VP + nt * 8 + g];
                    mma8(o[nt], a, b0, b1);
                }
            }
        }
        __syncthreads();
    }

    // epilogue -> g_O (B,T,C), tf32-rounded for out-proj cp.async path
    const float inv0 = 1.0f / l0, inv1 = 1.0f / l1;
    const int b = bh >> 4;
    const int h = bh & 15;
    float* obase = g_O + ((size_t)b * TT + qt * 128) * CC + h * HD;
    const int r0 = wrow + g, r1 = r0 + 8;
    #pragma unroll
    for (int nt = 0; nt < 8; nt++) {
        const int col = nt * 8 + 2 * q;
        float2 v0 = make_float2(__uint_as_float(f2tf32(o[nt][0] * inv0)),
                                __uint_as_float(f2tf32(o[nt][1] * inv0)));
        float2 v1 = make_float2(__uint_as_float(f2tf32(o[nt][2] * inv1)),
                                __uint_as_float(f2tf32(o[nt][3] * inv1)));
        *(float2*)(obase + (size_t)r0 * CC + col) = v0;
        *(float2*)(obase + (size_t)r1 * CC + col) = v1;
    }
}

// ---------------------------------------------------------------------------
extern "C" void kernel_launch(void* const* d_in, const int* in_sizes, int n_in,
                              void* d_out, int out_size) {
    const float* x     = (const float*)d_in[0];
    const float* W_qkv = (const float*)d_in[1];
    const float* b_qkv = (const float*)d_in[2];
    const float* W_out = (const float*)d_in[3];
    const float* b_out = (const float*)d_in[4];
    float* out = (float*)d_out;

    // Idempotent, capture-safe, no static guards
    cudaFuncSetAttribute(flash_tc,
                         cudaFuncAttributeMaxDynamicSharedMemorySize,
                         FLASH_SMEM);
    cudaFuncSetAttribute(gemm_tc<0>,
                         cudaFuncAttributeMaxDynamicSharedMemorySize,
                         GEMM_SMEM);
    cudaFuncSetAttribute(gemm_tc<1>,
                         cudaFuncAttributeMaxDynamicSharedMemorySize,
                         GEMM_SMEM);

    // pre-round inputs to tf32
    round_tf32<<<(MM * CC / 4 + 255) / 256, 256>>>(x, 0, MM * CC);
    round_tf32<<<(CC * N_QKV / 4 + 255) / 256, 256>>>(W_qkv, 1, CC * N_QKV);
    round_tf32<<<(CC * CC / 4 + 255) / 256, 256>>>(W_out, 2, CC * CC);

    dim3 gQKV(N_QKV / 128, MM / 128);      // 24 x 64
    gemm_tc<0><<<gQKV, 128, GEMM_SMEM>>>(b_qkv, nullptr);

    dim3 gFA(TT / 128, BB * NH);           // 16 x 64
    flash_tc<<<gFA, 256, FLASH_SMEM>>>();

    dim3 gOUT(CC / 128, MM / 128);         // 8 x 64
    gemm_tc<1><<<gOUT, 128, GEMM_SMEM>>>(b_out, out);
}

// round 10
// speedup vs baseline: 1.7502x; 1.7502x over previous
#include <cuda_runtime.h>
#include <cuda_fp16.h>
#include <math.h>
#include <stdint.h>

// Shapes (fixed by the problem)
#define BB   4
#define TT   2048
#define CC   1024
#define NH   16
#define HD   64
#define MM   (BB*TT)          // 8192
#define N_QKV (3*CC)          // 3072

// ---------------------------------------------------------------------------
// Scratch (device globals; no allocation allowed). All fp16 operands.
// ---------------------------------------------------------------------------
__device__ __half g_Q [BB*NH*TT*HD];   // (B,H,T,D), Q pre-scaled by 1/8
__device__ __half g_K [BB*NH*TT*HD];   // (B,H,T,D)
__device__ __half g_Vt[BB*NH*HD*TT];   // (B,H,D,T)  V TRANSPOSED
__device__ __half g_O [MM*CC];         // (B,T,C) attention out
__device__ __half g_X16[MM*CC];        // fp16 x
__device__ __half g_W1t[N_QKV*CC];     // W_qkv^T [3072][1024]
__device__ __half g_W2t[CC*CC];        // W_out^T [1024][1024]

// ---------------------------------------------------------------------------
// Helpers
// ---------------------------------------------------------------------------
__device__ __forceinline__ uint32_t h2u(__half2 h) {
    // portable bitcast (no __half2_as_uint in this toolchain)
    uint32_t u;
    *(__half2*)&u = h;
    return u;
}

__device__ __forceinline__ void mma16(float c[4], const uint32_t a[4],
                                      uint32_t b0, uint32_t b1) {
    asm volatile(
        "mma.sync.aligned.m16n8k16.row.col.f32.f16.f16.f32 "
        "{%0,%1,%2,%3},{%4,%5,%6,%7},{%8,%9},{%0,%1,%2,%3};"
        : "+f"(c[0]), "+f"(c[1]), "+f"(c[2]), "+f"(c[3])
        : "r"(a[0]), "r"(a[1]), "r"(a[2]), "r"(a[3]), "r"(b0), "r"(b1));
}

__device__ __forceinline__ void cp16(uint32_t dst, const void* src) {
    asm volatile("cp.async.cg.shared.global [%0], [%1], 16;"
                 :: "r"(dst), "l"(src));
}
#define CP_COMMIT() asm volatile("cp.async.commit_group;")
#define CP_WAIT(n)  asm volatile("cp.async.wait_group %0;" :: "n"(n))

__device__ __forceinline__ uint32_t smem_u32(const void* p) {
    uint32_t a;
    asm("{ .reg .u64 t; cvta.to.shared.u64 t, %1; cvt.u32.u64 %0, t; }"
        : "=r"(a) : "l"(p));
    return a;
}

// ---------------------------------------------------------------------------
// Prep kernels: fp32 -> fp16
// ---------------------------------------------------------------------------
__global__ void to_half(const float* __restrict__ in, int n) {
    int i = (blockIdx.x * blockDim.x + threadIdx.x) * 4;
    if (i >= n) return;
    float4 v = *(const float4*)(in + i);
    __half2 h0 = __floats2half2_rn(v.x, v.y);
    __half2 h1 = __floats2half2_rn(v.z, v.w);
    *(uint2*)(g_X16 + i) = make_uint2(h2u(h0), h2u(h1));
}

// in: [CC][N] row-major fp32 -> out: [N][CC] fp16 (K-major)
__global__ void transpose_half(const float* __restrict__ in, int which) {
    __shared__ float tile[32][33];
    const int N = (which == 1) ? N_QKV : CC;
    __half* out = (which == 1) ? (__half*)g_W1t : (__half*)g_W2t;
    const int n0 = blockIdx.x * 32, k0 = blockIdx.y * 32;
    const int tx = threadIdx.x, ty = threadIdx.y;
    #pragma unroll
    for (int i = 0; i < 4; i++)
        tile[ty + 8*i][tx] = in[(size_t)(k0 + ty + 8*i) * N + n0 + tx];
    __syncthreads();
    #pragma unroll
    for (int i = 0; i < 4; i++)
        out[(size_t)(n0 + ty + 8*i) * CC + k0 + tx] =
            __float2half_rn(tile[tx][ty + 8*i]);
}

// ---------------------------------------------------------------------------
// FP16 GEMM, cp.async 4-stage pipeline, m16n8k16.
// BM=BN=128, BK=32 halfs, 128 threads (4 warps 2x2), warp tile 64x64.
// Rows padded to PAD=40 halfs (20 words; bank=(20g+q)%32 bijective).
// MODE 0: A=g_X16, B=g_W1t, scatter->g_Q/g_K/g_Vt.  MODE 1: A=g_O, B=g_W2t.
// ---------------------------------------------------------------------------
#define PAD   40                       // halfs per 32-half row
#define STG   4
#define TILEH (128*PAD)                // halfs per tile per stage
#define GEMM_SMEM (STG * 2 * TILEH * 2)    // 81920 bytes

template <int MODE>
__global__ __launch_bounds__(128) void gemm16(const float* __restrict__ bias,
                                              float* __restrict__ C) {
    extern __shared__ __half hsm[];
    __half* As = hsm;                   // [STG][TILEH]
    __half* Bs = hsm + STG * TILEH;     // [STG][TILEH]

    const __half* A = (MODE == 0) ? (const __half*)g_X16 : (const __half*)g_O;
    const __half* B = (MODE == 0) ? (const __half*)g_W1t : (const __half*)g_W2t;

    const int tid  = threadIdx.x;
    const int lane = tid & 31;
    const int g    = lane >> 2;
    const int q    = lane & 3;
    const int wid  = tid >> 5;
    const int wm   = (wid & 1) * 64;
    const int wn   = (wid >> 1) * 64;

    const int bm = blockIdx.y * 128;
    const int bn = blockIdx.x * 128;

    const uint32_t sA = smem_u32(As);
    const uint32_t sB = smem_u32(Bs);

    auto fill = [&](int s, int k0) {
        const __half* ap = A + (size_t)(bm + tid) * CC + k0;
        const __half* bp = B + (size_t)(bn + tid) * CC + k0;
        uint32_t da = sA + (uint32_t)(s * TILEH + tid * PAD) * 2;
        uint32_t db = sB + (uint32_t)(s * TILEH + tid * PAD) * 2;
        cp16(da,      ap);      cp16(da + 16, ap + 8);
        cp16(da + 32, ap + 16); cp16(da + 48, ap + 24);
        cp16(db,      bp);      cp16(db + 16, bp + 8);
        cp16(db + 32, bp + 16); cp16(db + 48, bp + 24);
    };

    float c[4][8][4];
    #pragma unroll
    for (int mt = 0; mt < 4; mt++)
        #pragma unroll
        for (int nt = 0; nt < 8; nt++)
            #pragma unroll
            for (int r = 0; r < 4; r++) c[mt][nt][r] = 0.0f;

    const int NT = CC / 32;   // 32 stages
    fill(0, 0);  CP_COMMIT();
    fill(1, 32); CP_COMMIT();
    fill(2, 64); CP_COMMIT();

    for (int t = 0; t < NT; t++) {
        CP_WAIT(2);
        __syncthreads();

        const int tn = t + 3;
        if (tn < NT) fill(tn & (STG - 1), tn * 32);
        CP_COMMIT();

        const uint32_t* Au = (const uint32_t*)(As + (t & (STG - 1)) * TILEH);
        const uint32_t* Bu = (const uint32_t*)(Bs + (t & (STG - 1)) * TILEH);

        #pragma unroll
        for (int kw = 0; kw < 16; kw += 8) {   // word offset: 0, 8 (k=0,16)
            uint32_t af[4][4];
            #pragma unroll
            for (int mt = 0; mt < 4; mt++) {
                const int rb = wm + mt * 16;
                af[mt][0] = Au[(rb + g)     * 20 + kw + q];
                af[mt][1] = Au[(rb + g + 8) * 20 + kw + q];
                af[mt][2] = Au[(rb + g)     * 20 + kw + q + 4];
                af[mt][3] = Au[(rb + g + 8) * 20 + kw + q + 4];
            }
            #pragma unroll
            for (int nt = 0; nt < 8; nt++) {
                uint32_t b0 = Bu[(wn + nt * 8 + g) * 20 + kw + q];
                uint32_t b1 = Bu[(wn + nt * 8 + g) * 20 + kw + q + 4];
                #pragma unroll
                for (int mt = 0; mt < 4; mt++)
                    mma16(c[mt][nt], af[mt], b0, b1);
            }
        }
    }

    // epilogue
    #pragma unroll
    for (int mt = 0; mt < 4; mt++) {
        #pragma unroll
        for (int nt = 0; nt < 8; nt++) {
            #pragma unroll
            for (int r = 0; r < 4; r++) {
                int row = bm + wm + mt * 16 + g + (r >> 1) * 8;
                int col = bn + wn + nt * 8 + q * 2 + (r & 1);
                float v = c[mt][nt][r] + bias[col];
                if (MODE == 0) {
                    int b  = row >> 11;
                    int tt = row & 2047;
                    int which = col >> 10;
                    int cc = col & 1023;
                    int h = cc >> 6;
                    int d = cc & 63;
                    size_t bh = (size_t)(b * NH + h);
                    if (which == 0)
                        g_Q[(bh * TT + tt) * HD + d] = __float2half_rn(v * 0.125f);
                    else if (which == 1)
                        g_K[(bh * TT + tt) * HD + d] = __float2half_rn(v);
                    else
                        g_Vt[(bh * HD + d) * TT + tt] = __float2half_rn(v);
                } else {
                    C[(size_t)row * CC + col] = v;
                }
            }
        }
    }
}

// ---------------------------------------------------------------------------
// Flash attention, fp16 m16n8k16, cp.async double-buffered KV.
// 256 threads (8 warps), 128 queries/CTA, 64-key tiles. V pre-transposed.
// Row pads 72 halfs (36 words; bank=(4g+q)%32 bijective).
// ---------------------------------------------------------------------------
#define KPH 72
#define VPH 72
#define PPH 72
#define FLASH_SMEM ((2*64*KPH + 2*64*VPH + 128*PPH) * 2)

__global__ __launch_bounds__(256) void flash16() {
    extern __shared__ __half fsm[];
    __half* Ks = fsm;                         // [2][64*KPH]  (key rows, d cols)
    __half* Vs = fsm + 2 * 64 * KPH;          // [2][64*VPH]  (d rows, key cols)
    __half* Ps = fsm + 2 * 64 * KPH + 2 * 64 * VPH;  // [128*PPH]

    const int tid  = threadIdx.x;
    const int lane = tid & 31;
    const int g    = lane >> 2;
    const int q    = lane & 3;
    const int w    = tid >> 5;
    const int wrow = w * 16;

    const int qt = (int)(gridDim.x - 1) - (int)blockIdx.x;  // big tiles first
    const int bh = blockIdx.y;
    const int nkv = 2 * qt + 2;

    // Q fragments: 4 k-steps (k16 each) x 4 regs, fp16 pre-scaled
    const __half* Qp = g_Q + ((size_t)bh * TT + qt * 128) * HD;
    uint32_t qa[4][4];
    #pragma unroll
    for (int ks = 0; ks < 4; ks++) {
        const int r0 = wrow + g, r1 = r0 + 8;
        const int c0 = ks * 16 + 2 * q;
        qa[ks][0] = *(const uint32_t*)(Qp + r0 * HD + c0);
        qa[ks][1] = *(const uint32_t*)(Qp + r1 * HD + c0);
        qa[ks][2] = *(const uint32_t*)(Qp + r0 * HD + c0 + 8);
        qa[ks][3] = *(const uint32_t*)(Qp + r1 * HD + c0 + 8);
    }

    float o[8][4];
    #pragma unroll
    for (int nt = 0; nt < 8; nt++)
        #pragma unroll
        for (int r = 0; r < 4; r++) o[nt][r] = 0.0f;
    float m0 = -INFINITY, m1 = -INFINITY, l0 = 0.0f, l1 = 0.0f;

    const uint32_t sK = smem_u32(Ks);
    const uint32_t sV = smem_u32(Vs);
    const int frow  = tid >> 2;         // 0..63
    const int fcolh = (tid & 3) * 16;   // half index: 0,16,32,48

    auto fillkv = [&](int buf, int kti) {
        const __half* Kp = g_K + ((size_t)bh * TT + kti * 64 + frow) * HD + fcolh;
        const __half* Vp = g_Vt + ((size_t)bh * HD + frow) * TT + kti * 64 + fcolh;
        uint32_t dk = sK + (uint32_t)(buf * 64 * KPH + frow * KPH + fcolh) * 2;
        uint32_t dv = sV + (uint32_t)(buf * 64 * VPH + frow * VPH + fcolh) * 2;
        cp16(dk,      Kp);
        cp16(dk + 16, Kp + 8);
        cp16(dv,      Vp);
        cp16(dv + 16, Vp + 8);
    };

    fillkv(0, 0); CP_COMMIT();

    for (int ktt = 0; ktt < nkv; ktt++) {
        if (ktt + 1 < nkv) fillkv((ktt + 1) & 1, ktt + 1);
        CP_COMMIT();
        CP_WAIT(1);
        __syncthreads();

        const bool full_skip = (ktt * 64) > (qt * 128 + wrow + 15);
        if (!full_skip) {
            const uint32_t* Kb = (const uint32_t*)(Ks + (ktt & 1) * 64 * KPH);
            const uint32_t* Vb = (const uint32_t*)(Vs + (ktt & 1) * 64 * VPH);

            // S = Q K^T  (B frag: rows=key n, k=d contiguous)
            float s[8][4];
            #pragma unroll
            for (int nt = 0; nt < 8; nt++)
                #pragma unroll
                for (int r = 0; r < 4; r++) s[nt][r] = 0.0f;

            #pragma unroll
            for (int ks = 0; ks < 4; ks++) {
                #pragma unroll
                for (int nt = 0; nt < 8; nt++) {
                    uint32_t b0 = Kb[(nt * 8 + g) * 36 + ks * 8 + q];
                    uint32_t b1 = Kb[(nt * 8 + g) * 36 + ks * 8 + q + 4];
                    mma16(s[nt], qa[ks], b0, b1);
                }
            }

            // causal mask (global indices)
            const int rowg0 = qt * 128 + wrow + g;
            const int rowg1 = rowg0 + 8;
            if (ktt * 64 + 63 > qt * 128 + wrow) {
                #pragma unroll
                for (int nt = 0; nt < 8; nt++) {
                    const int c0 = ktt * 64 + nt * 8 + 2 * q;
                    if (c0     > rowg0) s[nt][0] = -INFINITY;
                    if (c0 + 1 > rowg0) s[nt][1] = -INFINITY;
                    if (c0     > rowg1) s[nt][2] = -INFINITY;
                    if (c0 + 1 > rowg1) s[nt][3] = -INFINITY;
                }
            }

            // online softmax (quad reduction)
            float mx0 = -INFINITY, mx1 = -INFINITY;
            #pragma unroll
            for (int nt = 0; nt < 8; nt++) {
                mx0 = fmaxf(mx0, fmaxf(s[nt][0], s[nt][1]));
                mx1 = fmaxf(mx1, fmaxf(s[nt][2], s[nt][3]));
            }
            mx0 = fmaxf(mx0, __shfl_xor_sync(0xffffffffu, mx0, 1));
            mx0 = fmaxf(mx0, __shfl_xor_sync(0xffffffffu, mx0, 2));
            mx1 = fmaxf(mx1, __shfl_xor_sync(0xffffffffu, mx1, 1));
            mx1 = fmaxf(mx1, __shfl_xor_sync(0xffffffffu, mx1, 2));

            float mn0 = fmaxf(m0, mx0), mn1 = fmaxf(m1, mx1);
            float corr0 = __expf(m0 - mn0), corr1 = __expf(m1 - mn1);
            m0 = mn0; m1 = mn1;

            float rs0 = 0.0f, rs1 = 0.0f;
            #pragma unroll
            for (int nt = 0; nt < 8; nt++) {
                s[nt][0] = __expf(s[nt][0] - m0); rs0 += s[nt][0];
                s[nt][1] = __expf(s[nt][1] - m0); rs0 += s[nt][1];
                s[nt][2] = __expf(s[nt][2] - m1); rs1 += s[nt][2];
                s[nt][3] = __expf(s[nt][3] - m1); rs1 += s[nt][3];
            }
            rs0 += __shfl_xor_sync(0xffffffffu, rs0, 1);
            rs0 += __shfl_xor_sync(0xffffffffu, rs0, 2);
            rs1 += __shfl_xor_sync(0xffffffffu, rs1, 1);
            rs1 += __shfl_xor_sync(0xffffffffu, rs1, 2);
            l0 = l0 * corr0 + rs0;
            l1 = l1 * corr1 + rs1;

            #pragma unroll
            for (int nt = 0; nt < 8; nt++) {
                o[nt][0] *= corr0; o[nt][1] *= corr0;
                o[nt][2] *= corr1; o[nt][3] *= corr1;
            }

            // P -> smem fp16 (own warp rows; no barrier)
            uint32_t* Pu = (uint32_t*)Ps;
            #pragma unroll
            for (int nt = 0; nt < 8; nt++) {
                const int cw = (nt * 8 + 2 * q) >> 1;   // word index (4nt+q)
                __half2 p0 = __floats2half2_rn(s[nt][0], s[nt][1]);
                __half2 p1 = __floats2half2_rn(s[nt][2], s[nt][3]);
                Pu[(wrow + g)     * 36 + cw] = h2u(p0);
                Pu[(wrow + g + 8) * 36 + cw] = h2u(p1);
            }

            // O += P V  (A=P rows=query, k=key; B=V^T rows=d, k=key)
            #pragma unroll
            for (int kk = 0; kk < 4; kk++) {
                uint32_t a[4];
                a[0] = Pu[(wrow + g)     * 36 + kk * 8 + q];
                a[1] = Pu[(wrow + g + 8) * 36 + kk * 8 + q];
                a[2] = Pu[(wrow + g)     * 36 + kk * 8 + q + 4];
                a[3] = Pu[(wrow + g + 8) * 36 + kk * 8 + q + 4];
                #pragma unroll
                for (int nt = 0; nt < 8; nt++) {
                    uint32_t b0 = Vb[(nt * 8 + g) * 36 + kk * 8 + q];
                    uint32_t b1 = Vb[(nt * 8 + g) * 36 + kk * 8 + q + 4];
                    mma16(o[nt], a, b0, b1);
                }
            }
        }
        __syncthreads();
    }

    // epilogue -> g_O fp16 (B,T,C)
    const float inv0 = 1.0f / l0, inv1 = 1.0f / l1;
    const int b = bh >> 4;
    const int h = bh & 15;
    __half* obase = g_O + ((size_t)b * TT + qt * 128) * CC + h * HD;
    const int r0 = wrow + g, r1 = r0 + 8;
    #pragma unroll
    for (int nt = 0; nt < 8; nt++) {
        const int col = nt * 8 + 2 * q;
        __half2 v0 = __floats2half2_rn(o[nt][0] * inv0, o[nt][1] * inv0);
        __half2 v1 = __floats2half2_rn(o[nt][2] * inv1, o[nt][3] * inv1);
        *(__half2*)(obase + (size_t)r0 * CC + col) = v0;
        *(__half2*)(obase + (size_t)r1 * CC + col) = v1;
    }
}

// ---------------------------------------------------------------------------
extern "C" void kernel_launch(void* const* d_in, const int* in_sizes, int n_in,
                              void* d_out, int out_size) {
    const float* x     = (const float*)d_in[0];
    const float* W_qkv = (const float*)d_in[1];
    const float* b_qkv = (const float*)d_in[2];
    const float* W_out = (const float*)d_in[3];
    const float* b_out = (const float*)d_in[4];
    float* out = (float*)d_out;

    cudaFuncSetAttribute(flash16,
                         cudaFuncAttributeMaxDynamicSharedMemorySize,
                         FLASH_SMEM);
    cudaFuncSetAttribute(gemm16<0>,
                         cudaFuncAttributeMaxDynamicSharedMemorySize,
                         GEMM_SMEM);
    cudaFuncSetAttribute(gemm16<1>,
                         cudaFuncAttributeMaxDynamicSharedMemorySize,
                         GEMM_SMEM);

    // prep: x -> fp16; weights -> fp16 transposed [N][K]
    to_half<<<(MM * CC / 4 + 255) / 256, 256>>>(x, MM * CC);
    dim3 gT1(N_QKV / 32, CC / 32);
    transpose_half<<<gT1, dim3(32, 8)>>>(W_qkv, 1);
    dim3 gT2(CC / 32, CC / 32);
    transpose_half<<<gT2, dim3(32, 8)>>>(W_out, 2);

    dim3 gQKV(N_QKV / 128, MM / 128);      // 24 x 64
    gemm16<0><<<gQKV, 128, GEMM_SMEM>>>(b_qkv, nullptr);

    dim3 gFA(TT / 128, BB * NH);           // 16 x 64
    flash16<<<gFA, 256, FLASH_SMEM>>>();

    dim3 gOUT(CC / 128, MM / 128);         // 8 x 64
    gemm16<1><<<gOUT, 128, GEMM_SMEM>>>(b_out, out);
}

// round 11
// speedup vs baseline: 2.0993x; 1.1995x over previous
#include <cuda_runtime.h>
#include <cuda_fp16.h>
#include <math.h>
#include <stdint.h>

// Shapes (fixed by the problem)
#define BB   4
#define TT   2048
#define CC   1024
#define NH   16
#define HD   64
#define MM   (BB*TT)          // 8192
#define N_QKV (3*CC)          // 3072

// ---------------------------------------------------------------------------
// Scratch (device globals; no allocation allowed). All fp16 operands.
// ---------------------------------------------------------------------------
__device__ __half g_Q [BB*NH*TT*HD];   // (B,H,T,D), Q pre-scaled by 1/8
__device__ __half g_K [BB*NH*TT*HD];   // (B,H,T,D)
__device__ __half g_Vt[BB*NH*HD*TT];   // (B,H,D,T)  V TRANSPOSED
__device__ __half g_O [MM*CC];         // (B,T,C) attention out
__device__ __half g_X16[MM*CC];        // fp16 x
__device__ __half g_W1t[N_QKV*CC];     // W_qkv^T [3072][1024]
__device__ __half g_W2t[CC*CC];        // W_out^T [1024][1024]

// ---------------------------------------------------------------------------
// Helpers
// ---------------------------------------------------------------------------
__device__ __forceinline__ uint32_t h2u(__half2 h) {
    uint32_t u;
    *(__half2*)&u = h;
    return u;
}

__device__ __forceinline__ void mma16(float c[4], const uint32_t a[4],
                                      uint32_t b0, uint32_t b1) {
    asm volatile(
        "mma.sync.aligned.m16n8k16.row.col.f32.f16.f16.f32 "
        "{%0,%1,%2,%3},{%4,%5,%6,%7},{%8,%9},{%0,%1,%2,%3};"
        : "+f"(c[0]), "+f"(c[1]), "+f"(c[2]), "+f"(c[3])
        : "r"(a[0]), "r"(a[1]), "r"(a[2]), "r"(a[3]), "r"(b0), "r"(b1));
}

__device__ __forceinline__ void ldsm4(uint32_t r[4], uint32_t addr) {
    asm volatile(
        "ldmatrix.sync.aligned.m8n8.x4.shared.b16 {%0,%1,%2,%3}, [%4];"
        : "=r"(r[0]), "=r"(r[1]), "=r"(r[2]), "=r"(r[3]) : "r"(addr));
}

__device__ __forceinline__ void cp16(uint32_t dst, const void* src) {
    asm volatile("cp.async.cg.shared.global [%0], [%1], 16;"
                 :: "r"(dst), "l"(src));
}
#define CP_COMMIT() asm volatile("cp.async.commit_group;")
#define CP_WAIT(n)  asm volatile("cp.async.wait_group %0;" :: "n"(n))

__device__ __forceinline__ uint32_t smem_u32(const void* p) {
    uint32_t a;
    asm("{ .reg .u64 t; cvta.to.shared.u64 t, %1; cvt.u32.u64 %0, t; }"
        : "=r"(a) : "l"(p));
    return a;
}

// ---------------------------------------------------------------------------
// Prep kernels: fp32 -> fp16
// ---------------------------------------------------------------------------
__global__ void to_half(const float* __restrict__ in, int n) {
    int i = (blockIdx.x * blockDim.x + threadIdx.x) * 4;
    if (i >= n) return;
    float4 v = *(const float4*)(in + i);
    __half2 h0 = __floats2half2_rn(v.x, v.y);
    __half2 h1 = __floats2half2_rn(v.z, v.w);
    *(uint2*)(g_X16 + i) = make_uint2(h2u(h0), h2u(h1));
}

// in: [CC][N] row-major fp32 -> out: [N][CC] fp16 (K-major)
__global__ void transpose_half(const float* __restrict__ in, int which) {
    __shared__ float tile[32][33];
    const int N = (which == 1) ? N_QKV : CC;
    __half* out = (which == 1) ? (__half*)g_W1t : (__half*)g_W2t;
    const int n0 = blockIdx.x * 32, k0 = blockIdx.y * 32;
    const int tx = threadIdx.x, ty = threadIdx.y;
    #pragma unroll
    for (int i = 0; i < 4; i++)
        tile[ty + 8*i][tx] = in[(size_t)(k0 + ty + 8*i) * N + n0 + tx];
    __syncthreads();
    #pragma unroll
    for (int i = 0; i < 4; i++)
        out[(size_t)(n0 + ty + 8*i) * CC + k0 + tx] =
            __float2half_rn(tile[tx][ty + 8*i]);
}

// ---------------------------------------------------------------------------
// FP16 GEMM v3: ldmatrix fragments + 256 threads.
// BM=BN=128, BK=32 halfs, 8 warps (4x2), warp tile 32x64.
// PAD=40 halfs/row: both cp.async fill and all LDSM phases conflict-free
// (20*r mod 32 covers all banks over any 8 consecutive rows).
// MODE 0: A=g_X16, B=g_W1t, scatter->g_Q/g_K/g_Vt.  MODE 1: A=g_O, B=g_W2t.
// ---------------------------------------------------------------------------
#define PAD   40                        // halfs per 32-half row
#define STG   4
#define TILEH (128*PAD)                 // halfs per tile per stage
#define TILEB (TILEH*2)                 // bytes
#define GEMM_SMEM (STG * 2 * TILEB)     // 81920 bytes

template <int MODE>
__global__ __launch_bounds__(256, 2) void gemm16(const float* __restrict__ bias,
                                                 float* __restrict__ C) {
    extern __shared__ __half hsm[];
    __half* As = hsm;                   // [STG][TILEH]
    __half* Bs = hsm + STG * TILEH;     // [STG][TILEH]

    const __half* A = (MODE == 0) ? (const __half*)g_X16 : (const __half*)g_O;
    const __half* B = (MODE == 0) ? (const __half*)g_W1t : (const __half*)g_W2t;

    const int tid  = threadIdx.x;
    const int lane = tid & 31;
    const int g    = lane >> 2;
    const int q    = lane & 3;
    const int wid  = tid >> 5;          // 0..7
    const int wm   = (wid & 3) * 32;    // warp M offset (4 rows of warps)
    const int wn   = (wid >> 2) * 64;   // warp N offset (2 cols)

    const int bm = blockIdx.y * 128;
    const int bn = blockIdx.x * 128;

    const uint32_t sA = smem_u32(As);
    const uint32_t sB = smem_u32(Bs);

    // ldmatrix lane addressing: lanes 0-15 -> rows, lanes 16-31 -> +8 halfs
    const int lr = lane & 15;
    const int lc = (lane >> 4) * 8;

    // fill: 256 threads, each does half a row (16 halfs) of A and of B
    const int frow = tid >> 1;          // 0..127
    const int fc   = (tid & 1) * 16;    // 0 or 16 halfs
    auto fill = [&](int s, int k0) {
        const __half* ap = A + (size_t)(bm + frow) * CC + k0 + fc;
        const __half* bp = B + (size_t)(bn + frow) * CC + k0 + fc;
        uint32_t da = sA + (uint32_t)(s * TILEH + frow * PAD + fc) * 2;
        uint32_t db = sB + (uint32_t)(s * TILEH + frow * PAD + fc) * 2;
        cp16(da, ap); cp16(da + 16, ap + 8);
        cp16(db, bp); cp16(db + 16, bp + 8);
    };

    float c[2][8][4];
    #pragma unroll
    for (int mt = 0; mt < 2; mt++)
        #pragma unroll
        for (int nt = 0; nt < 8; nt++)
            #pragma unroll
            for (int r = 0; r < 4; r++) c[mt][nt][r] = 0.0f;

    const int NT = CC / 32;   // 32 stages
    fill(0, 0);  CP_COMMIT();
    fill(1, 32); CP_COMMIT();
    fill(2, 64); CP_COMMIT();

    for (int t = 0; t < NT; t++) {
        CP_WAIT(2);
        __syncthreads();

        const int tn = t + 3;
        if (tn < NT) fill(tn & (STG - 1), tn * 32);
        CP_COMMIT();

        const uint32_t aoff = sA + (uint32_t)(t & (STG - 1)) * TILEB;
        const uint32_t boff = sB + (uint32_t)(t & (STG - 1)) * TILEB;

        #pragma unroll
        for (int kw = 0; kw < 32; kw += 16) {   // k halfs 0, 16
            uint32_t a[2][4];
            #pragma unroll
            for (int mt = 0; mt < 2; mt++)
                ldsm4(a[mt],
                      aoff + (uint32_t)((wm + mt * 16 + lr) * PAD + kw + lc) * 2);
            #pragma unroll
            for (int nt2 = 0; nt2 < 4; nt2++) {
                uint32_t b[4];
                ldsm4(b,
                      boff + (uint32_t)((wn + nt2 * 16 + lr) * PAD + kw + lc) * 2);
                // b[0]=b0 of nt even, b[1]=b0 of nt odd, b[2]/b[3] = b1's
                mma16(c[0][2 * nt2],     a[0], b[0], b[2]);
                mma16(c[1][2 * nt2],     a[1], b[0], b[2]);
                mma16(c[0][2 * nt2 + 1], a[0], b[1], b[3]);
                mma16(c[1][2 * nt2 + 1], a[1], b[1], b[3]);
            }
        }
    }

    // epilogue
    #pragma unroll
    for (int mt = 0; mt < 2; mt++) {
        #pragma unroll
        for (int nt = 0; nt < 8; nt++) {
            #pragma unroll
            for (int r = 0; r < 4; r++) {
                int row = bm + wm + mt * 16 + g + (r >> 1) * 8;
                int col = bn + wn + nt * 8 + q * 2 + (r & 1);
                float v = c[mt][nt][r] + bias[col];
                if (MODE == 0) {
                    int b  = row >> 11;
                    int tt = row & 2047;
                    int which = col >> 10;
                    int cc = col & 1023;
                    int h = cc >> 6;
                    int d = cc & 63;
                    size_t bh = (size_t)(b * NH + h);
                    if (which == 0)
                        g_Q[(bh * TT + tt) * HD + d] = __float2half_rn(v * 0.125f);
                    else if (which == 1)
                        g_K[(bh * TT + tt) * HD + d] = __float2half_rn(v);
                    else
                        g_Vt[(bh * HD + d) * TT + tt] = __float2half_rn(v);
                } else {
                    C[(size_t)row * CC + col] = v;
                }
            }
        }
    }
}

// ---------------------------------------------------------------------------
// Flash attention (byte-identical to R10 — passed; do not touch this round).
// ---------------------------------------------------------------------------
#define KPH 72
#define VPH 72
#define PPH 72
#define FLASH_SMEM ((2*64*KPH + 2*64*VPH + 128*PPH) * 2)

__global__ __launch_bounds__(256) void flash16() {
    extern __shared__ __half fsm[];
    __half* Ks = fsm;                         // [2][64*KPH]
    __half* Vs = fsm + 2 * 64 * KPH;          // [2][64*VPH]
    __half* Ps = fsm + 2 * 64 * KPH + 2 * 64 * VPH;  // [128*PPH]

    const int tid  = threadIdx.x;
    const int lane = tid & 31;
    const int g    = lane >> 2;
    const int q    = lane & 3;
    const int w    = tid >> 5;
    const int wrow = w * 16;

    const int qt = (int)(gridDim.x - 1) - (int)blockIdx.x;
    const int bh = blockIdx.y;
    const int nkv = 2 * qt + 2;

    const __half* Qp = g_Q + ((size_t)bh * TT + qt * 128) * HD;
    uint32_t qa[4][4];
    #pragma unroll
    for (int ks = 0; ks < 4; ks++) {
        const int r0 = wrow + g, r1 = r0 + 8;
        const int c0 = ks * 16 + 2 * q;
        qa[ks][0] = *(const uint32_t*)(Qp + r0 * HD + c0);
        qa[ks][1] = *(const uint32_t*)(Qp + r1 * HD + c0);
        qa[ks][2] = *(const uint32_t*)(Qp + r0 * HD + c0 + 8);
        qa[ks][3] = *(const uint32_t*)(Qp + r1 * HD + c0 + 8);
    }

    float o[8][4];
    #pragma unroll
    for (int nt = 0; nt < 8; nt++)
        #pragma unroll
        for (int r = 0; r < 4; r++) o[nt][r] = 0.0f;
    float m0 = -INFINITY, m1 = -INFINITY, l0 = 0.0f, l1 = 0.0f;

    const uint32_t sK = smem_u32(Ks);
    const uint32_t sV = smem_u32(Vs);
    const int frow  = tid >> 2;
    const int fcolh = (tid & 3) * 16;

    auto fillkv = [&](int buf, int kti) {
        const __half* Kp = g_K + ((size_t)bh * TT + kti * 64 + frow) * HD + fcolh;
        const __half* Vp = g_Vt + ((size_t)bh * HD + frow) * TT + kti * 64 + fcolh;
        uint32_t dk = sK + (uint32_t)(buf * 64 * KPH + frow * KPH + fcolh) * 2;
        uint32_t dv = sV + (uint32_t)(buf * 64 * VPH + frow * VPH + fcolh) * 2;
        cp16(dk,      Kp);
        cp16(dk + 16, Kp + 8);
        cp16(dv,      Vp);
        cp16(dv + 16, Vp + 8);
    };

    fillkv(0, 0); CP_COMMIT();

    for (int ktt = 0; ktt < nkv; ktt++) {
        if (ktt + 1 < nkv) fillkv((ktt + 1) & 1, ktt + 1);
        CP_COMMIT();
        CP_WAIT(1);
        __syncthreads();

        const bool full_skip = (ktt * 64) > (qt * 128 + wrow + 15);
        if (!full_skip) {
            const uint32_t* Kb = (const uint32_t*)(Ks + (ktt & 1) * 64 * KPH);
            const uint32_t* Vb = (const uint32_t*)(Vs + (ktt & 1) * 64 * VPH);

            float s[8][4];
            #pragma unroll
            for (int nt = 0; nt < 8; nt++)
                #pragma unroll
                for (int r = 0; r < 4; r++) s[nt][r] = 0.0f;

            #pragma unroll
            for (int ks = 0; ks < 4; ks++) {
                #pragma unroll
                for (int nt = 0; nt < 8; nt++) {
                    uint32_t b0 = Kb[(nt * 8 + g) * 36 + ks * 8 + q];
                    uint32_t b1 = Kb[(nt * 8 + g) * 36 + ks * 8 + q + 4];
                    mma16(s[nt], qa[ks], b0, b1);
                }
            }

            const int rowg0 = qt * 128 + wrow + g;
            const int rowg1 = rowg0 + 8;
            if (ktt * 64 + 63 > qt * 128 + wrow) {
                #pragma unroll
                for (int nt = 0; nt < 8; nt++) {
                    const int c0 = ktt * 64 + nt * 8 + 2 * q;
                    if (c0     > rowg0) s[nt][0] = -INFINITY;
                    if (c0 + 1 > rowg0) s[nt][1] = -INFINITY;
                    if (c0     > rowg1) s[nt][2] = -INFINITY;
                    if (c0 + 1 > rowg1) s[nt][3] = -INFINITY;
                }
            }

            float mx0 = -INFINITY, mx1 = -INFINITY;
            #pragma unroll
            for (int nt = 0; nt < 8; nt++) {
                mx0 = fmaxf(mx0, fmaxf(s[nt][0], s[nt][1]));
                mx1 = fmaxf(mx1, fmaxf(s[nt][2], s[nt][3]));
            }
            mx0 = fmaxf(mx0, __shfl_xor_sync(0xffffffffu, mx0, 1));
            mx0 = fmaxf(mx0, __shfl_xor_sync(0xffffffffu, mx0, 2));
            mx1 = fmaxf(mx1, __shfl_xor_sync(0xffffffffu, mx1, 1));
            mx1 = fmaxf(mx1, __shfl_xor_sync(0xffffffffu, mx1, 2));

            float mn0 = fmaxf(m0, mx0), mn1 = fmaxf(m1, mx1);
            float corr0 = __expf(m0 - mn0), corr1 = __expf(m1 - mn1);
            m0 = mn0; m1 = mn1;

            float rs0 = 0.0f, rs1 = 0.0f;
            #pragma unroll
            for (int nt = 0; nt < 8; nt++) {
                s[nt][0] = __expf(s[nt][0] - m0); rs0 += s[nt][0];
                s[nt][1] = __expf(s[nt][1] - m0); rs0 += s[nt][1];
                s[nt][2] = __expf(s[nt][2] - m1); rs1 += s[nt][2];
                s[nt][3] = __expf(s[nt][3] - m1); rs1 += s[nt][3];
            }
            rs0 += __shfl_xor_sync(0xffffffffu, rs0, 1);
            rs0 += __shfl_xor_sync(0xffffffffu, rs0, 2);
            rs1 += __shfl_xor_sync(0xffffffffu, rs1, 1);
            rs1 += __shfl_xor_sync(0xffffffffu, rs1, 2);
            l0 = l0 * corr0 + rs0;
            l1 = l1 * corr1 + rs1;

            #pragma unroll
            for (int nt = 0; nt < 8; nt++) {
                o[nt][0] *= corr0; o[nt][1] *= corr0;
                o[nt][2] *= corr1; o[nt][3] *= corr1;
            }

            uint32_t* Pu = (uint32_t*)Ps;
            #pragma unroll
            for (int nt = 0; nt < 8; nt++) {
                const int cw = (nt * 8 + 2 * q) >> 1;
                __half2 p0 = __floats2half2_rn(s[nt][0], s[nt][1]);
                __half2 p1 = __floats2half2_rn(s[nt][2], s[nt][3]);
                Pu[(wrow + g)     * 36 + cw] = h2u(p0);
                Pu[(wrow + g + 8) * 36 + cw] = h2u(p1);
            }

            #pragma unroll
            for (int kk = 0; kk < 4; kk++) {
                uint32_t a[4];
                a[0] = Pu[(wrow + g)     * 36 + kk * 8 + q];
                a[1] = Pu[(wrow + g + 8) * 36 + kk * 8 + q];
                a[2] = Pu[(wrow + g)     * 36 + kk * 8 + q + 4];
                a[3] = Pu[(wrow + g + 8) * 36 + kk * 8 + q + 4];
                #pragma unroll
                for (int nt = 0; nt < 8; nt++) {
                    uint32_t b0 = Vb[(nt * 8 + g) * 36 + kk * 8 + q];
                    uint32_t b1 = Vb[(nt * 8 + g) * 36 + kk * 8 + q + 4];
                    mma16(o[nt], a, b0, b1);
                }
            }
        }
        __syncthreads();
    }

    const float inv0 = 1.0f / l0, inv1 = 1.0f / l1;
    const int b = bh >> 4;
    const int h = bh & 15;
    __half* obase = g_O + ((size_t)b * TT + qt * 128) * CC + h * HD;
    const int r0 = wrow + g, r1 = r0 + 8;
    #pragma unroll
    for (int nt = 0; nt < 8; nt++) {
        const int col = nt * 8 + 2 * q;
        __half2 v0 = __floats2half2_rn(o[nt][0] * inv0, o[nt][1] * inv0);
        __half2 v1 = __floats2half2_rn(o[nt][2] * inv1, o[nt][3] * inv1);
        *(__half2*)(obase + (size_t)r0 * CC + col) = v0;
        *(__half2*)(obase + (size_t)r1 * CC + col) = v1;
    }
}

// ---------------------------------------------------------------------------
extern "C" void kernel_launch(void* const* d_in, const int* in_sizes, int n_in,
                              void* d_out, int out_size) {
    const float* x     = (const float*)d_in[0];
    const float* W_qkv = (const float*)d_in[1];
    const float* b_qkv = (const float*)d_in[2];
    const float* W_out = (const float*)d_in[3];
    const float* b_out = (const float*)d_in[4];
    float* out = (float*)d_out;

    cudaFuncSetAttribute(flash16,
                         cudaFuncAttributeMaxDynamicSharedMemorySize,
                         FLASH_SMEM);
    cudaFuncSetAttribute(gemm16<0>,
                         cudaFuncAttributeMaxDynamicSharedMemorySize,
                         GEMM_SMEM);
    cudaFuncSetAttribute(gemm16<1>,
                         cudaFuncAttributeMaxDynamicSharedMemorySize,
                         GEMM_SMEM);

    // prep: x -> fp16; weights -> fp16 transposed [N][K]
    to_half<<<(MM * CC / 4 + 255) / 256, 256>>>(x, MM * CC);
    dim3 gT1(N_QKV / 32, CC / 32);
    transpose_half<<<gT1, dim3(32, 8)>>>(W_qkv, 1);
    dim3 gT2(CC / 32, CC / 32);
    transpose_half<<<gT2, dim3(32, 8)>>>(W_out, 2);

    dim3 gQKV(N_QKV / 128, MM / 128);      // 24 x 64
    gemm16<0><<<gQKV, 256, GEMM_SMEM>>>(b_qkv, nullptr);

    dim3 gFA(TT / 128, BB * NH);           // 16 x 64
    flash16<<<gFA, 256, FLASH_SMEM>>>();

    dim3 gOUT(CC / 128, MM / 128);         // 8 x 64
    gemm16<1><<<gOUT, 256, GEMM_SMEM>>>(b_out, out);
}